// round 10
// baseline (speedup 1.0000x reference)
#include <cuda_runtime.h>
#include <math.h>

#define VOCAB 50257
#define HID   1024
#define H2    2048
#define H3    3072
#define MAXLEN 64
#define GRID 148
#define NT 512
#define NW (GRID * 16)          // 2368 warps
#define NUNITS16 3142           // ceil(VOCAB / 16)
#define BIG_NEG (-3.0e38f)

// ---------------- scratch ----------------
__device__ unsigned g_leaf[16];   // self-resetting leaf counters
__device__ unsigned g_root;       // self-resetting root counter
__device__ unsigned g_gen;        // monotone across replays
__device__ unsigned g_work;
__device__ float g_logits[MAXLEN];
__device__ float g_cat[H2];
__device__ float g_xp[H2];
__device__ float g_gi[H3];
__device__ float g_gh[H3];
__device__ float g_pm[GRID];
__device__ float g_ps[GRID];

__device__ __forceinline__ float warp_sum(float v) {
#pragma unroll
    for (int o = 16; o; o >>= 1) v += __shfl_xor_sync(0xffffffffu, v, o);
    return v;
}

__device__ __forceinline__ float dot4(float4 a, float4 b) {
    return a.x * b.x + a.y * b.y + a.z * b.z + a.w * b.w;
}

__device__ __forceinline__ void lse_update(float& m, float& s, float x) {
    float M = fmaxf(m, x);
    s = s * __expf(m - M) + __expf(x - M);
    m = M;
}

__device__ __forceinline__ void lse_merge(float& m, float& s, float m2, float s2) {
    float M = fmaxf(m, m2);
    s = s * __expf(m - M) + s2 * __expf(m2 - M);
    m = M;
}

// hierarchical grid barrier: 148 arrivals spread over 16 leaves -> 1 root.
// Safe: 148 CTAs, 1/SM, all co-resident. Leaf/root self-reset; g_gen monotone.
__device__ __forceinline__ void gsync() {
    __syncthreads();
    if (threadIdx.x == 0) {
        __threadfence();
        const int leaf = blockIdx.x & 15;
        const unsigned leaf_cnt = (leaf < 4) ? 10u : 9u;   // 148 = 4*10 + 12*9
        unsigned my = *(volatile unsigned*)&g_gen;
        if (atomicAdd(&g_leaf[leaf], 1u) == leaf_cnt - 1u) {
            g_leaf[leaf] = 0;
            __threadfence();
            if (atomicAdd(&g_root, 1u) == 15u) {
                g_root = 0;
                __threadfence();
                atomicAdd(&g_gen, 1u);
            }
        }
        while (*(volatile unsigned*)&g_gen == my) { }
        __threadfence();
    }
    __syncthreads();
}

__global__ void __launch_bounds__(NT, 1) k_fused(
    const int* __restrict__ inp,
    const float* __restrict__ hidden,
    const float* __restrict__ enc,
    const float* __restrict__ emb,
    const float* __restrict__ attn_W,
    const float* __restrict__ attn_b,
    const float* __restrict__ comb_W,
    const float* __restrict__ comb_b,
    const float* __restrict__ Wih,
    const float* __restrict__ Whh,
    const float* __restrict__ bih,
    const float* __restrict__ bhh,
    const float* __restrict__ out_W,
    const float* __restrict__ out_b,
    float* __restrict__ dout)
{
    __shared__ float sw[MAXLEN];
    __shared__ float spart[4][128];
    __shared__ float svec[HID];       // phase3: x ; phase4: h_new
    __shared__ float rm[16], rs[16];
    __shared__ float sm[NT], ss[NT];

    const int t = threadIdx.x;
    const int b = blockIdx.x;
    const int wid = t >> 5, lane = t & 31;
    const int GW = b * 16 + wid;

    const float4* h4 = (const float4*)hidden;

    // ======== Phase 0: attn logits (warps 0..63) || Whh gates (2 rows concurrent) ========
    if (b == 0 && t == 0) g_work = 0;   // ordered by gsyncs before phase 4
    if (GW < 64) {
        const int row = GW;
        const float4* er4 = (const float4*)(emb + (size_t)inp[0] * HID);
        const float4* wr = (const float4*)(attn_W + (size_t)row * H2);
        float acc = 0.f;
#pragma unroll
        for (int i = 0; i < 16; i++) {
            int off = lane + 32 * i;
            float4 v = (i < 8) ? er4[off] : h4[off - 256];
            acc += dot4(wr[off], v);
        }
        acc = warp_sum(acc);
        if (lane == 0) g_logits[row] = acc + attn_b[row];
    } else {
        const int w = GW - 64;            // 0..2303
        const int r0 = w;                 // < 3072 always
        const int r1 = w + (NW - 64);     // < 3072 only for w < 768
        const bool has1 = (r1 < H3);
        const float4* w0 = (const float4*)(Whh + (size_t)r0 * HID);
        const float4* w1 = (const float4*)(Whh + (size_t)(has1 ? r1 : r0) * HID);
        float a0 = 0.f, a1 = 0.f;
#pragma unroll
        for (int i = 0; i < 8; i++) {
            int off = lane + 32 * i;
            float4 v = h4[off];
            a0 += dot4(w0[off], v);
            a1 += dot4(w1[off], v);
        }
        a0 = warp_sum(a0);
        a1 = warp_sum(a1);
        if (lane == 0) {
            g_gh[r0] = a0 + bhh[r0];
            if (has1) g_gh[r1] = a1 + bhh[r1];
        }
    }
    gsync();

    // ======== Phase 1: softmax+applied+cat (blocks 0..7); idle: bulk L2 prefetch ========
    if (b < 8) {
        if (t < MAXLEN) sw[t] = g_logits[t];
        __syncthreads();
        if (t < 32) {
            float a = sw[t], c = sw[t + 32];
            float m = fmaxf(a, c);
#pragma unroll
            for (int o = 16; o; o >>= 1) m = fmaxf(m, __shfl_xor_sync(0xffffffffu, m, o));
            float e0 = __expf(a - m), e1 = __expf(c - m);
            float s = e0 + e1;
#pragma unroll
            for (int o = 16; o; o >>= 1) s += __shfl_xor_sync(0xffffffffu, s, o);
            sw[t] = e0 / s;
            sw[t + 32] = e1 / s;
            if (b == 0) {
                dout[VOCAB + HID + t] = sw[t];
                dout[VOCAB + HID + t + 32] = sw[t + 32];
            }
        }
        __syncthreads();
        int j = b * 128 + (t & 127);
        int isl = t >> 7;                 // 0..3
        float a = 0.f;
#pragma unroll
        for (int k = 0; k < 16; k++) {
            int i = isl + 4 * k;
            a += sw[i] * enc[i * HID + j];
        }
        spart[isl][t & 127] = a;
        __syncthreads();
        if (t < 128) {
            float s = spart[0][t] + spart[1][t] + spart[2][t] + spart[3][t];
            g_cat[HID + j] = s;
            g_cat[j] = emb[(size_t)inp[0] * HID + j];
        }
    } else if (lane == 0) {
        // fire-and-forget 48KB bulk prefetch: 140 blocks * 16 warps = 105MB of out_W
        int W2 = (b - 8) * 16 + wid;       // 0..2239
        const char* src = (const char*)out_W + (size_t)W2 * 49152;
        asm volatile("cp.async.bulk.prefetch.L2.global [%0], %1;"
                     :: "l"(src), "r"(49152) : "memory");
    }
    gsync();

    // ======== Phase 2: combine split-K=2 partials (2048 warps) ========
    if (GW < 2048) {
        int row = GW >> 1, half = GW & 1;
        const float4* wr = (const float4*)(comb_W + (size_t)row * H2) + half * 256;
        const float4* c4 = (const float4*)g_cat + half * 256;
        float acc = 0.f;
#pragma unroll
        for (int i = 0; i < 8; i++) {
            int off = lane + 32 * i;
            acc += dot4(wr[off], c4[off]);
        }
        acc = warp_sum(acc);
        if (lane == 0) g_xp[row + half * HID] = acc;
    }
    gsync();

    // ======== Phase 3: x = relu(p0+p1+b) ; gi = Wih@x (2 rows concurrent) ========
    {
        for (int k = t; k < HID; k += NT)
            svec[k] = fmaxf(g_xp[k] + g_xp[k + HID] + comb_b[k], 0.f);
        __syncthreads();
        const float4* x4 = (const float4*)svec;
        const int r0 = GW;                // < 3072 always (2368 warps)
        const int r1 = GW + NW;           // < 3072 only for GW < 704
        const bool has1 = (r1 < H3);
        const float4* w0 = (const float4*)(Wih + (size_t)r0 * HID);
        const float4* w1 = (const float4*)(Wih + (size_t)(has1 ? r1 : r0) * HID);
        float a0 = 0.f, a1 = 0.f;
#pragma unroll
        for (int i = 0; i < 8; i++) {
            int off = lane + 32 * i;
            float4 v = x4[off];
            a0 += dot4(w0[off], v);
            a1 += dot4(w1[off], v);
        }
        a0 = warp_sum(a0);
        a1 = warp_sum(a1);
        if (lane == 0) {
            g_gi[r0] = a0 + bih[r0];
            if (has1) g_gi[r1] = a1 + bih[r1];
        }
    }
    gsync();

    // ======== Phase 4: h_new (redundant) + 16-row-steal out-proj + online LSE ========
    __syncthreads();   // svec reuse: all phase-3 readers done (gsync above)
    for (int k = t; k < HID; k += NT) {
        float r = 1.f / (1.f + __expf(-(g_gi[k] + g_gh[k])));
        float z = 1.f / (1.f + __expf(-(g_gi[k + HID] + g_gh[k + HID])));
        float n = tanhf(g_gi[k + 2 * HID] + r * g_gh[k + 2 * HID]);
        float hnew = (1.f - z) * n + z * hidden[k];
        svec[k] = hnew;
        if (b == 0) dout[VOCAB + k] = hnew;
    }
    __syncthreads();
    {
        const float4* sv4 = (const float4*)svec;
        float wm = BIG_NEG, ws = 0.f;
        while (true) {
            int u;
            if (lane == 0) u = (int)atomicAdd(&g_work, 1u);
            u = __shfl_sync(0xffffffffu, u, 0);
            if (u >= NUNITS16) break;
#pragma unroll
            for (int p = 0; p < 2; p++) {
                int row0 = u * 16 + p * 8;
                if (row0 >= VOCAB) break;
                const float4* rp[8];
#pragma unroll
                for (int r = 0; r < 8; r++) {
                    int row = row0 + r;
                    if (row >= VOCAB) row = VOCAB - 1;
                    rp[r] = (const float4*)(out_W + (size_t)row * HID);
                }
                float acc[8];
#pragma unroll
                for (int r = 0; r < 8; r++) acc[r] = 0.f;
#pragma unroll
                for (int i = 0; i < 8; i++) {
                    int off = lane + 32 * i;
                    float4 v = sv4[off];
#pragma unroll
                    for (int r = 0; r < 8; r++) acc[r] += dot4(rp[r][off], v);
                }
#pragma unroll
                for (int r = 0; r < 8; r++) acc[r] = warp_sum(acc[r]);
                if (lane == 0) {
#pragma unroll
                    for (int r = 0; r < 8; r++) {
                        int row = row0 + r;
                        if (row < VOCAB) {
                            float l = acc[r] + out_b[row];
                            dout[row] = l;
                            lse_update(wm, ws, l);
                        }
                    }
                }
            }
        }
        if (lane == 0) { rm[wid] = wm; rs[wid] = ws; }
    }
    __syncthreads();
    if (t == 0) {
        float m = BIG_NEG, s = 0.f;
#pragma unroll
        for (int i = 0; i < 16; i++) lse_merge(m, s, rm[i], rs[i]);
        g_pm[b] = m;
        g_ps[b] = s;
    }
    gsync();

    // ======== Phase 5: merge partials (redundant) + subtract ========
    {
        float m = BIG_NEG, s = 0.f;
        if (t < GRID) { m = g_pm[t]; s = g_ps[t]; }
        sm[t] = m;
        ss[t] = s;
        __syncthreads();
        for (int o = 128; o; o >>= 1) {
            if (t < o) lse_merge(sm[t], ss[t], sm[t + o], ss[t + o]);
            __syncthreads();
        }
        float lse = sm[0] + __logf(ss[0]);
        for (int i = b * NT + t; i < VOCAB; i += GRID * NT) dout[i] -= lse;
    }
}

// ---------------- launcher ----------------
extern "C" void kernel_launch(void* const* d_in, const int* in_sizes, int n_in,
                              void* d_out, int out_size) {
    const int*   inp    = (const int*)d_in[0];
    const float* hidden = (const float*)d_in[1];
    const float* enc    = (const float*)d_in[2];
    const float* emb    = (const float*)d_in[3];
    const float* attn_W = (const float*)d_in[4];
    const float* attn_b = (const float*)d_in[5];
    const float* comb_W = (const float*)d_in[6];
    const float* comb_b = (const float*)d_in[7];
    const float* Wih    = (const float*)d_in[8];
    const float* Whh    = (const float*)d_in[9];
    const float* bih    = (const float*)d_in[10];
    const float* bhh    = (const float*)d_in[11];
    const float* out_W  = (const float*)d_in[12];
    const float* out_b  = (const float*)d_in[13];
    float* out = (float*)d_out;

    k_fused<<<GRID, NT>>>(inp, hidden, enc, emb, attn_W, attn_b,
                          comb_W, comb_b, Wih, Whh, bih, bhh,
                          out_W, out_b, out);
}

// round 11
// speedup vs baseline: 1.0211x; 1.0211x over previous
#include <cuda_runtime.h>
#include <math.h>

#define VOCAB 50257
#define HID   1024
#define H2    2048
#define H3    3072
#define MAXLEN 64
#define GRID 148
#define NT 512
#define NW (GRID * 16)          // 2368 warps
#define NUNITS16 3142           // ceil(VOCAB / 16)
#define BIG_NEG (-3.0e38f)

// ---------------- scratch ----------------
__device__ unsigned g_cnt;
__device__ unsigned g_gen;
__device__ unsigned g_work;
__device__ float g_logits[MAXLEN];
__device__ float g_cat[H2];
__device__ float g_xp[H2];
__device__ float g_gi[H3];
__device__ float g_gh[H3];
__device__ float g_pm[GRID];
__device__ float g_ps[GRID];

__device__ __forceinline__ float warp_sum(float v) {
#pragma unroll
    for (int o = 16; o; o >>= 1) v += __shfl_xor_sync(0xffffffffu, v, o);
    return v;
}

__device__ __forceinline__ float dot4(float4 a, float4 b) {
    return a.x * b.x + a.y * b.y + a.z * b.z + a.w * b.w;
}

__device__ __forceinline__ void lse_update(float& m, float& s, float x) {
    float M = fmaxf(m, x);
    s = s * __expf(m - M) + __expf(x - M);
    m = M;
}

__device__ __forceinline__ void lse_merge(float& m, float& s, float m2, float s2) {
    float M = fmaxf(m, m2);
    s = s * __expf(m - M) + s2 * __expf(m2 - M);
    m = M;
}

// grid barrier; safe: GRID (148) <= #SMs so all CTAs co-resident
__device__ __forceinline__ void gsync() {
    __syncthreads();
    if (threadIdx.x == 0) {
        __threadfence();
        unsigned my = *(volatile unsigned*)&g_gen;
        unsigned old = atomicAdd(&g_cnt, 1u);
        if (old == GRID - 1) {
            g_cnt = 0;
            __threadfence();
            atomicAdd(&g_gen, 1u);
        } else {
            while (*(volatile unsigned*)&g_gen == my) { }
        }
        __threadfence();
    }
    __syncthreads();
}

__global__ void __launch_bounds__(NT, 1) k_fused(
    const int* __restrict__ inp,
    const float* __restrict__ hidden,
    const float* __restrict__ enc,
    const float* __restrict__ emb,
    const float* __restrict__ attn_W,
    const float* __restrict__ attn_b,
    const float* __restrict__ comb_W,
    const float* __restrict__ comb_b,
    const float* __restrict__ Wih,
    const float* __restrict__ Whh,
    const float* __restrict__ bih,
    const float* __restrict__ bhh,
    const float* __restrict__ out_W,
    const float* __restrict__ out_b,
    float* __restrict__ dout)
{
    __shared__ float sw[MAXLEN];
    __shared__ float spart[4][128];
    __shared__ float svec[HID];       // phase3: x ; phase4: h_new
    __shared__ float rm[16], rs[16];
    __shared__ float sm[NT], ss[NT];

    const int t = threadIdx.x;
    const int b = blockIdx.x;
    const int wid = t >> 5, lane = t & 31;
    const int GW = b * 16 + wid;

    const float4* h4 = (const float4*)hidden;

    // ======== Phase 0: attn logits (warps 0..63) || Whh gates (rest) ========
    if (b == 0 && t == 0) g_work = 0;   // ordered by gsyncs before phase 4
    if (GW < 64) {
        const int row = GW;
        const float4* er4 = (const float4*)(emb + (size_t)inp[0] * HID);
        const float4* wr = (const float4*)(attn_W + (size_t)row * H2);
        float acc = 0.f;
#pragma unroll
        for (int i = 0; i < 16; i++) {
            int off = lane + 32 * i;
            float4 v = (i < 8) ? er4[off] : h4[off - 256];
            acc += dot4(wr[off], v);
        }
        acc = warp_sum(acc);
        if (lane == 0) g_logits[row] = acc + attn_b[row];
    } else {
        for (int r = GW - 64; r < H3; r += NW - 64) {
            const float4* wr = (const float4*)(Whh + (size_t)r * HID);
            float acc = 0.f;
#pragma unroll
            for (int i = 0; i < 8; i++) {
                int off = lane + 32 * i;
                acc += dot4(wr[off], h4[off]);
            }
            acc = warp_sum(acc);
            if (lane == 0) g_gh[r] = acc + bhh[r];
        }
    }
    gsync();

    // ======== Phase 1: softmax + attn_applied + cat (blocks 0..7) ========
    //          idle blocks: one bulk L2 prefetch instruction per warp over out_W
    if (b < 8) {
        if (t < MAXLEN) sw[t] = g_logits[t];
        __syncthreads();
        if (t < 32) {
            float a = sw[t], c = sw[t + 32];
            float m = fmaxf(a, c);
#pragma unroll
            for (int o = 16; o; o >>= 1) m = fmaxf(m, __shfl_xor_sync(0xffffffffu, m, o));
            float e0 = __expf(a - m), e1 = __expf(c - m);
            float s = e0 + e1;
#pragma unroll
            for (int o = 16; o; o >>= 1) s += __shfl_xor_sync(0xffffffffu, s, o);
            sw[t] = e0 / s;
            sw[t + 32] = e1 / s;
            if (b == 0) {
                dout[VOCAB + HID + t] = sw[t];
                dout[VOCAB + HID + t + 32] = sw[t + 32];
            }
        }
        __syncthreads();
        int j = b * 128 + (t & 127);
        int isl = t >> 7;                 // 0..3
        float a = 0.f;
#pragma unroll
        for (int k = 0; k < 16; k++) {
            int i = isl + 4 * k;
            a += sw[i] * enc[i * HID + j];
        }
        spart[isl][t & 127] = a;
        __syncthreads();
        if (t < 128) {
            float s = spart[0][t] + spart[1][t] + spart[2][t] + spart[3][t];
            g_cat[HID + j] = s;
            g_cat[j] = emb[(size_t)inp[0] * HID + j];
        }
    } else if (lane == 0) {
        // fire-and-forget 48KB bulk prefetch: 140 blocks * 16 warps = 105MB of out_W
        int W2 = (b - 8) * 16 + wid;       // 0..2239
        const char* src = (const char*)out_W + (size_t)W2 * 49152;
        asm volatile("cp.async.bulk.prefetch.L2.global [%0], %1;"
                     :: "l"(src), "r"(49152) : "memory");
    }
    gsync();

    // ======== Phase 2: combine split-K=2 partials (2048 warps) ========
    //          idle warps: extend out_W prefetch coverage 105 -> ~120MB
    if (GW < 2048) {
        int row = GW >> 1, half = GW & 1;
        const float4* wr = (const float4*)(comb_W + (size_t)row * H2) + half * 256;
        const float4* c4 = (const float4*)g_cat + half * 256;
        float acc = 0.f;
#pragma unroll
        for (int i = 0; i < 8; i++) {
            int off = lane + 32 * i;
            acc += dot4(wr[off], c4[off]);
        }
        acc = warp_sum(acc);
        if (lane == 0) g_xp[row + half * HID] = acc;
    } else if (lane == 0) {
        int idx = GW - 2048;               // 0..319
        const char* src = (const char*)out_W + (size_t)2240 * 49152 + (size_t)idx * 49152;
        asm volatile("cp.async.bulk.prefetch.L2.global [%0], %1;"
                     :: "l"(src), "r"(49152) : "memory");
    }
    gsync();

    // ======== Phase 3: x = relu(p0+p1+b) (per-block smem) ; gi = Wih@x ========
    {
        for (int k = t; k < HID; k += NT)
            svec[k] = fmaxf(g_xp[k] + g_xp[k + HID] + comb_b[k], 0.f);
        __syncthreads();
        const float4* x4 = (const float4*)svec;
        for (int r = GW; r < H3; r += NW) {
            const float4* wr = (const float4*)(Wih + (size_t)r * HID);
            float acc = 0.f;
#pragma unroll
            for (int i = 0; i < 8; i++) {
                int off = lane + 32 * i;
                acc += dot4(wr[off], x4[off]);
            }
            acc = warp_sum(acc);
            if (lane == 0) g_gi[r] = acc + bih[r];
        }
    }
    gsync();

    // ======== Phase 4: h_new (redundant) + 16-row-steal out-proj + online LSE ========
    __syncthreads();   // svec reuse: all phase-3 readers done (gsync above)
    for (int k = t; k < HID; k += NT) {
        float r = 1.f / (1.f + __expf(-(g_gi[k] + g_gh[k])));
        float z = 1.f / (1.f + __expf(-(g_gi[k + HID] + g_gh[k + HID])));
        float n = tanhf(g_gi[k + 2 * HID] + r * g_gh[k + 2 * HID]);
        float hnew = (1.f - z) * n + z * hidden[k];
        svec[k] = hnew;
        if (b == 0) dout[VOCAB + k] = hnew;
    }
    __syncthreads();
    {
        const float4* sv4 = (const float4*)svec;
        float wm = BIG_NEG, ws = 0.f;
        while (true) {
            int u;
            if (lane == 0) u = (int)atomicAdd(&g_work, 1u);
            u = __shfl_sync(0xffffffffu, u, 0);
            if (u >= NUNITS16) break;
#pragma unroll
            for (int p = 0; p < 2; p++) {
                int row0 = u * 16 + p * 8;
                if (row0 >= VOCAB) break;
                const float4* rp[8];
#pragma unroll
                for (int r = 0; r < 8; r++) {
                    int row = row0 + r;
                    if (row >= VOCAB) row = VOCAB - 1;
                    rp[r] = (const float4*)(out_W + (size_t)row * HID);
                }
                float acc[8];
#pragma unroll
                for (int r = 0; r < 8; r++) acc[r] = 0.f;
#pragma unroll
                for (int i = 0; i < 8; i++) {
                    int off = lane + 32 * i;
                    float4 v = sv4[off];
#pragma unroll
                    for (int r = 0; r < 8; r++) acc[r] += dot4(rp[r][off], v);
                }
#pragma unroll
                for (int r = 0; r < 8; r++) acc[r] = warp_sum(acc[r]);
                if (lane == 0) {
#pragma unroll
                    for (int r = 0; r < 8; r++) {
                        int row = row0 + r;
                        if (row < VOCAB) {
                            float l = acc[r] + out_b[row];
                            dout[row] = l;
                            lse_update(wm, ws, l);
                        }
                    }
                }
            }
        }
        if (lane == 0) { rm[wid] = wm; rs[wid] = ws; }
    }
    __syncthreads();
    if (t == 0) {
        float m = BIG_NEG, s = 0.f;
#pragma unroll
        for (int i = 0; i < 16; i++) lse_merge(m, s, rm[i], rs[i]);
        g_pm[b] = m;
        g_ps[b] = s;
    }
    gsync();

    // ======== Phase 5: merge partials (redundant) + subtract ========
    {
        float m = BIG_NEG, s = 0.f;
        if (t < GRID) { m = g_pm[t]; s = g_ps[t]; }
        sm[t] = m;
        ss[t] = s;
        __syncthreads();
        for (int o = 128; o; o >>= 1) {
            if (t < o) lse_merge(sm[t], ss[t], sm[t + o], ss[t + o]);
            __syncthreads();
        }
        float lse = sm[0] + __logf(ss[0]);
        for (int i = b * NT + t; i < VOCAB; i += GRID * NT) dout[i] -= lse;
    }
}

// ---------------- launcher ----------------
extern "C" void kernel_launch(void* const* d_in, const int* in_sizes, int n_in,
                              void* d_out, int out_size) {
    const int*   inp    = (const int*)d_in[0];
    const float* hidden = (const float*)d_in[1];
    const float* enc    = (const float*)d_in[2];
    const float* emb    = (const float*)d_in[3];
    const float* attn_W = (const float*)d_in[4];
    const float* attn_b = (const float*)d_in[5];
    const float* comb_W = (const float*)d_in[6];
    const float* comb_b = (const float*)d_in[7];
    const float* Wih    = (const float*)d_in[8];
    const float* Whh    = (const float*)d_in[9];
    const float* bih    = (const float*)d_in[10];
    const float* bhh    = (const float*)d_in[11];
    const float* out_W  = (const float*)d_in[12];
    const float* out_b  = (const float*)d_in[13];
    float* out = (float*)d_out;

    k_fused<<<GRID, NT>>>(inp, hidden, enc, emb, attn_W, attn_b,
                          comb_W, comb_b, Wih, Whh, bih, bhh,
                          out_W, out_b, out);
}

// round 12
// speedup vs baseline: 1.0567x; 1.0349x over previous
#include <cuda_runtime.h>
#include <math.h>

#define VOCAB 50257
#define HID   1024
#define H2    2048
#define H3    3072
#define MAXLEN 64
#define GRID 148
#define NT 512
#define NW (GRID * 16)          // 2368 warps
#define NGROUPS 6283            // ceil(VOCAB / 8)
#define BIG_NEG (-3.0e38f)

// ---------------- scratch ----------------
__device__ unsigned g_cnt;
__device__ unsigned g_gen;      // monotone across replays
__device__ unsigned g_work;
__device__ unsigned g_attn_done;
__device__ float g_logits[MAXLEN];
__device__ float g_cat[H2];
__device__ float g_xp[H2];
__device__ float g_gi[H3];
__device__ float g_gh[H3];
__device__ float g_pm[GRID];
__device__ float g_ps[GRID];

__device__ __forceinline__ float warp_sum(float v) {
#pragma unroll
    for (int o = 16; o; o >>= 1) v += __shfl_xor_sync(0xffffffffu, v, o);
    return v;
}

__device__ __forceinline__ float dot4(float4 a, float4 b) {
    return a.x * b.x + a.y * b.y + a.z * b.z + a.w * b.w;
}

__device__ __forceinline__ void lse_update(float& m, float& s, float x) {
    float M = fmaxf(m, x);
    s = s * __expf(m - M) + __expf(x - M);
    m = M;
}

__device__ __forceinline__ void lse_merge(float& m, float& s, float m2, float s2) {
    float M = fmaxf(m, m2);
    s = s * __expf(m - M) + s2 * __expf(m2 - M);
    m = M;
}

// grid barrier; safe: GRID (148) <= #SMs so all CTAs co-resident
__device__ __forceinline__ void gsync() {
    __syncthreads();
    if (threadIdx.x == 0) {
        __threadfence();
        unsigned my = *(volatile unsigned*)&g_gen;
        unsigned old = atomicAdd(&g_cnt, 1u);
        if (old == GRID - 1) {
            g_cnt = 0;
            __threadfence();
            atomicAdd(&g_gen, 1u);
        } else {
            while (*(volatile unsigned*)&g_gen == my) { }
        }
        __threadfence();
    }
    __syncthreads();
}

__global__ void __launch_bounds__(NT, 1) k_fused(
    const int* __restrict__ inp,
    const float* __restrict__ hidden,
    const float* __restrict__ enc,
    const float* __restrict__ emb,
    const float* __restrict__ attn_W,
    const float* __restrict__ attn_b,
    const float* __restrict__ comb_W,
    const float* __restrict__ comb_b,
    const float* __restrict__ Wih,
    const float* __restrict__ Whh,
    const float* __restrict__ bih,
    const float* __restrict__ bhh,
    const float* __restrict__ out_W,
    const float* __restrict__ out_b,
    float* __restrict__ dout)
{
    __shared__ float sw[MAXLEN];
    __shared__ float spart[4][128];
    __shared__ float svec[HID];       // phase3: x ; phase4: h_new
    __shared__ float rm[16], rs[16];
    __shared__ float sm[NT], ss[NT];

    const int t = threadIdx.x;
    const int b = blockIdx.x;
    const int wid = t >> 5, lane = t & 31;
    const int GW = b * 16 + wid;

    const float4* h4 = (const float4*)hidden;

    // ======== Phase 0+1 merged ========
    // blocks 0..3  : attn logits (1 row/warp) -> signal g_attn_done
    // blocks 0..7  : spin on g_attn_done, then softmax + applied + cat
    // blocks 4..147: Whh gates; blocks 8..147 then bulk-L2 prefetch of out_W
    if (b == 0 && t == 0) g_work = 0;   // ordered before phase 4 by gsyncs
    if (GW < 64) {
        const int row = GW;
        const float4* er4 = (const float4*)(emb + (size_t)inp[0] * HID);
        const float4* wr = (const float4*)(attn_W + (size_t)row * H2);
        float acc = 0.f;
#pragma unroll
        for (int i = 0; i < 16; i++) {
            int off = lane + 32 * i;
            float4 v = (i < 8) ? er4[off] : h4[off - 256];
            acc += dot4(wr[off], v);
        }
        acc = warp_sum(acc);
        if (lane == 0) g_logits[row] = acc + attn_b[row];
    } else {
        for (int r = GW - 64; r < H3; r += NW - 64) {
            const float4* wr = (const float4*)(Whh + (size_t)r * HID);
            float acc = 0.f;
#pragma unroll
            for (int i = 0; i < 8; i++) {
                int off = lane + 32 * i;
                acc += dot4(wr[off], h4[off]);
            }
            acc = warp_sum(acc);
            if (lane == 0) g_gh[r] = acc + bhh[r];
        }
    }

    if (b < 4) {
        // publish attn logits
        __syncthreads();
        if (t == 0) {
            __threadfence();
            atomicAdd(&g_attn_done, 1u);
        }
    }

    if (b < 8) {
        // consume attn logits: softmax + applied + cat
        if (t == 0) {
            while (*(volatile unsigned*)&g_attn_done < 4u) { }
            __threadfence();
        }
        __syncthreads();
        if (t < MAXLEN) sw[t] = g_logits[t];
        __syncthreads();
        if (t < 32) {
            float a = sw[t], c = sw[t + 32];
            float m = fmaxf(a, c);
#pragma unroll
            for (int o = 16; o; o >>= 1) m = fmaxf(m, __shfl_xor_sync(0xffffffffu, m, o));
            float e0 = __expf(a - m), e1 = __expf(c - m);
            float s = e0 + e1;
#pragma unroll
            for (int o = 16; o; o >>= 1) s += __shfl_xor_sync(0xffffffffu, s, o);
            sw[t] = e0 / s;
            sw[t + 32] = e1 / s;
            if (b == 0) {
                dout[VOCAB + HID + t] = sw[t];
                dout[VOCAB + HID + t + 32] = sw[t + 32];
            }
        }
        __syncthreads();
        int j = b * 128 + (t & 127);
        int isl = t >> 7;                 // 0..3
        float a = 0.f;
#pragma unroll
        for (int k = 0; k < 16; k++) {
            int i = isl + 4 * k;
            a += sw[i] * enc[i * HID + j];
        }
        spart[isl][t & 127] = a;
        __syncthreads();
        if (t < 128) {
            float s = spart[0][t] + spart[1][t] + spart[2][t] + spart[3][t];
            g_cat[HID + j] = s;
            g_cat[j] = emb[(size_t)inp[0] * HID + j];
        }
    } else if (lane == 0) {
        // fire-and-forget 48KB bulk prefetch: 140 blocks * 16 warps = 105MB of out_W
        int W2 = (b - 8) * 16 + wid;       // 0..2239
        const char* src = (const char*)out_W + (size_t)W2 * 49152;
        asm volatile("cp.async.bulk.prefetch.L2.global [%0], %1;"
                     :: "l"(src), "r"(49152) : "memory");
    }
    gsync();

    // ======== Phase 2: combine split-K=2 partials (2048 warps) ========
    if (b == 0 && t == 0) g_attn_done = 0;   // all spins completed before gsync
    if (GW < 2048) {
        int row = GW >> 1, half = GW & 1;
        const float4* wr = (const float4*)(comb_W + (size_t)row * H2) + half * 256;
        const float4* c4 = (const float4*)g_cat + half * 256;
        float acc = 0.f;
#pragma unroll
        for (int i = 0; i < 8; i++) {
            int off = lane + 32 * i;
            acc += dot4(wr[off], c4[off]);
        }
        acc = warp_sum(acc);
        if (lane == 0) g_xp[row + half * HID] = acc;
    }
    gsync();

    // ======== Phase 3: x = relu(p0+p1+b) (per-block smem) ; gi = Wih@x ========
    {
        for (int k = t; k < HID; k += NT)
            svec[k] = fmaxf(g_xp[k] + g_xp[k + HID] + comb_b[k], 0.f);
        __syncthreads();
        const float4* x4 = (const float4*)svec;
        for (int r = GW; r < H3; r += NW) {
            const float4* wr = (const float4*)(Wih + (size_t)r * HID);
            float acc = 0.f;
#pragma unroll
            for (int i = 0; i < 8; i++) {
                int off = lane + 32 * i;
                acc += dot4(wr[off], x4[off]);
            }
            acc = warp_sum(acc);
            if (lane == 0) g_gi[r] = acc + bih[r];
        }
    }
    gsync();

    // ======== Phase 4: h_new (redundant) + work-stealing out-proj + online LSE ========
    __syncthreads();   // svec reuse: all phase-3 readers done (gsync above)
    for (int k = t; k < HID; k += NT) {
        float r = 1.f / (1.f + __expf(-(g_gi[k] + g_gh[k])));
        float z = 1.f / (1.f + __expf(-(g_gi[k + HID] + g_gh[k + HID])));
        float n = tanhf(g_gi[k + 2 * HID] + r * g_gh[k + 2 * HID]);
        float hnew = (1.f - z) * n + z * hidden[k];
        svec[k] = hnew;
        if (b == 0) dout[VOCAB + k] = hnew;
    }
    __syncthreads();
    {
        const float4* sv4 = (const float4*)svec;
        float wm = BIG_NEG, ws = 0.f;
        while (true) {
            int g;
            if (lane == 0) g = (int)atomicAdd(&g_work, 1u);
            g = __shfl_sync(0xffffffffu, g, 0);
            if (g >= NGROUPS) break;
            int row0 = g * 8;
            const float4* rp[8];
#pragma unroll
            for (int r = 0; r < 8; r++) {
                int row = row0 + r;
                if (row >= VOCAB) row = VOCAB - 1;
                rp[r] = (const float4*)(out_W + (size_t)row * HID);
            }
            float acc[8];
#pragma unroll
            for (int r = 0; r < 8; r++) acc[r] = 0.f;
#pragma unroll
            for (int i = 0; i < 8; i++) {
                int off = lane + 32 * i;
                float4 v = sv4[off];
#pragma unroll
                for (int r = 0; r < 8; r++) acc[r] += dot4(rp[r][off], v);
            }
#pragma unroll
            for (int r = 0; r < 8; r++) acc[r] = warp_sum(acc[r]);
            if (lane == 0) {
#pragma unroll
                for (int r = 0; r < 8; r++) {
                    int row = row0 + r;
                    if (row < VOCAB) {
                        float l = acc[r] + out_b[row];
                        dout[row] = l;
                        lse_update(wm, ws, l);
                    }
                }
            }
        }
        if (lane == 0) { rm[wid] = wm; rs[wid] = ws; }
    }
    __syncthreads();
    if (t == 0) {
        float m = BIG_NEG, s = 0.f;
#pragma unroll
        for (int i = 0; i < 16; i++) lse_merge(m, s, rm[i], rs[i]);
        g_pm[b] = m;
        g_ps[b] = s;
    }
    gsync();

    // ======== Phase 5: merge partials (redundant) + subtract ========
    {
        float m = BIG_NEG, s = 0.f;
        if (t < GRID) { m = g_pm[t]; s = g_ps[t]; }
        sm[t] = m;
        ss[t] = s;
        __syncthreads();
        for (int o = 128; o; o >>= 1) {
            if (t < o) lse_merge(sm[t], ss[t], sm[t + o], ss[t + o]);
            __syncthreads();
        }
        float lse = sm[0] + __logf(ss[0]);
        for (int i = b * NT + t; i < VOCAB; i += GRID * NT) dout[i] -= lse;
    }
}

// ---------------- launcher ----------------
extern "C" void kernel_launch(void* const* d_in, const int* in_sizes, int n_in,
                              void* d_out, int out_size) {
    const int*   inp    = (const int*)d_in[0];
    const float* hidden = (const float*)d_in[1];
    const float* enc    = (const float*)d_in[2];
    const float* emb    = (const float*)d_in[3];
    const float* attn_W = (const float*)d_in[4];
    const float* attn_b = (const float*)d_in[5];
    const float* comb_W = (const float*)d_in[6];
    const float* comb_b = (const float*)d_in[7];
    const float* Wih    = (const float*)d_in[8];
    const float* Whh    = (const float*)d_in[9];
    const float* bih    = (const float*)d_in[10];
    const float* bhh    = (const float*)d_in[11];
    const float* out_W  = (const float*)d_in[12];
    const float* out_b  = (const float*)d_in[13];
    float* out = (float*)d_out;

    k_fused<<<GRID, NT>>>(inp, hidden, enc, emb, attn_W, attn_b,
                          comb_W, comb_b, Wih, Whh, bih, bhh,
                          out_W, out_b, out);
}

// round 13
// speedup vs baseline: 1.1265x; 1.0661x over previous
#include <cuda_runtime.h>
#include <math.h>

#define VOCAB 50257
#define HID   1024
#define H2    2048
#define H3    3072
#define MAXLEN 64
#define GRID 148
#define NT 512
#define NW (GRID * 16)          // 2368 warps
#define NGROUPS 6283            // ceil(VOCAB / 8)
#define BIG_NEG (-3.0e38f)

// ---------------- scratch ----------------
__device__ unsigned g_cnt;
__device__ unsigned g_gen;
__device__ unsigned g_work;
__device__ float g_logits[MAXLEN];
__device__ float g_cat[H2];
__device__ float g_xp[H2];
__device__ float g_gi[H3];
__device__ float g_gh[H3];
__device__ float g_pm[GRID];
__device__ float g_ps[GRID];

__device__ __forceinline__ float warp_sum(float v) {
#pragma unroll
    for (int o = 16; o; o >>= 1) v += __shfl_xor_sync(0xffffffffu, v, o);
    return v;
}

__device__ __forceinline__ float dot4(float4 a, float4 b) {
    return a.x * b.x + a.y * b.y + a.z * b.z + a.w * b.w;
}

__device__ __forceinline__ void lse_update(float& m, float& s, float x) {
    float M = fmaxf(m, x);
    s = s * __expf(m - M) + __expf(x - M);
    m = M;
}

__device__ __forceinline__ void lse_merge(float& m, float& s, float m2, float s2) {
    float M = fmaxf(m, m2);
    s = s * __expf(m - M) + s2 * __expf(m2 - M);
    m = M;
}

// grid barrier; safe: GRID (148) <= #SMs so all CTAs co-resident
__device__ __forceinline__ void gsync() {
    __syncthreads();
    if (threadIdx.x == 0) {
        __threadfence();
        unsigned my = *(volatile unsigned*)&g_gen;
        unsigned old = atomicAdd(&g_cnt, 1u);
        if (old == GRID - 1) {
            g_cnt = 0;
            __threadfence();
            atomicAdd(&g_gen, 1u);
        } else {
            while (*(volatile unsigned*)&g_gen == my) { }
        }
        __threadfence();
    }
    __syncthreads();
}

__global__ void __launch_bounds__(NT, 1) k_fused(
    const int* __restrict__ inp,
    const float* __restrict__ hidden,
    const float* __restrict__ enc,
    const float* __restrict__ emb,
    const float* __restrict__ attn_W,
    const float* __restrict__ attn_b,
    const float* __restrict__ comb_W,
    const float* __restrict__ comb_b,
    const float* __restrict__ Wih,
    const float* __restrict__ Whh,
    const float* __restrict__ bih,
    const float* __restrict__ bhh,
    const float* __restrict__ out_W,
    const float* __restrict__ out_b,
    float* __restrict__ dout)
{
    __shared__ float sw[MAXLEN];
    __shared__ float spart[4][128];
    __shared__ float svec[HID];       // phase3: x ; phase4: h_new
    __shared__ float rm[16], rs[16];
    __shared__ float sm[NT], ss[NT];

    const int t = threadIdx.x;
    const int b = blockIdx.x;
    const int wid = t >> 5, lane = t & 31;
    const int GW = b * 16 + wid;

    const float4* h4 = (const float4*)hidden;

    // ======== startup: fire-and-forget L2 prefetch of comb_W + Wih (21MB) ========
    // phases 2-3 consume these; DRAM has idle headroom during phase 0.
    if (lane == 0) {
        const char* src;
        if (GW < 948) src = (const char*)comb_W + (size_t)GW * 8848;       // 8.39MB
        else          src = (const char*)Wih + (size_t)(GW - 948) * 8848;  // 12.56MB
        asm volatile("cp.async.bulk.prefetch.L2.global [%0], %1;"
                     :: "l"(src), "r"(8848) : "memory");
    }

    // ======== Phase 0: attn logits (warps 0..63) || Whh gates (rest) ========
    if (b == 0 && t == 0) g_work = 0;   // ordered by gsyncs before phase 4
    if (GW < 64) {
        const int row = GW;
        const float4* er4 = (const float4*)(emb + (size_t)inp[0] * HID);
        const float4* wr = (const float4*)(attn_W + (size_t)row * H2);
        float acc = 0.f;
#pragma unroll
        for (int i = 0; i < 16; i++) {
            int off = lane + 32 * i;
            float4 v = (i < 8) ? er4[off] : h4[off - 256];
            acc += dot4(wr[off], v);
        }
        acc = warp_sum(acc);
        if (lane == 0) g_logits[row] = acc + attn_b[row];
    } else {
        for (int r = GW - 64; r < H3; r += NW - 64) {
            const float4* wr = (const float4*)(Whh + (size_t)r * HID);
            float acc = 0.f;
#pragma unroll
            for (int i = 0; i < 8; i++) {
                int off = lane + 32 * i;
                acc += dot4(wr[off], h4[off]);
            }
            acc = warp_sum(acc);
            if (lane == 0) g_gh[r] = acc + bhh[r];
        }
    }
    gsync();

    // ======== Phase 1: softmax + attn_applied + cat (blocks 0..7) ========
    //          idle blocks: one bulk L2 prefetch instruction per warp over out_W
    if (b < 8) {
        if (t < MAXLEN) sw[t] = g_logits[t];
        __syncthreads();
        if (t < 32) {
            float a = sw[t], c = sw[t + 32];
            float m = fmaxf(a, c);
#pragma unroll
            for (int o = 16; o; o >>= 1) m = fmaxf(m, __shfl_xor_sync(0xffffffffu, m, o));
            float e0 = __expf(a - m), e1 = __expf(c - m);
            float s = e0 + e1;
#pragma unroll
            for (int o = 16; o; o >>= 1) s += __shfl_xor_sync(0xffffffffu, s, o);
            sw[t] = e0 / s;
            sw[t + 32] = e1 / s;
            if (b == 0) {
                dout[VOCAB + HID + t] = sw[t];
                dout[VOCAB + HID + t + 32] = sw[t + 32];
            }
        }
        __syncthreads();
        int j = b * 128 + (t & 127);
        int isl = t >> 7;                 // 0..3
        float a = 0.f;
#pragma unroll
        for (int k = 0; k < 16; k++) {
            int i = isl + 4 * k;
            a += sw[i] * enc[i * HID + j];
        }
        spart[isl][t & 127] = a;
        __syncthreads();
        if (t < 128) {
            float s = spart[0][t] + spart[1][t] + spart[2][t] + spart[3][t];
            g_cat[HID + j] = s;
            g_cat[j] = emb[(size_t)inp[0] * HID + j];
        }
    } else if (lane == 0) {
        // fire-and-forget 48KB bulk prefetch: 140 blocks * 16 warps = 105MB of out_W
        int W2 = (b - 8) * 16 + wid;       // 0..2239
        const char* src = (const char*)out_W + (size_t)W2 * 49152;
        asm volatile("cp.async.bulk.prefetch.L2.global [%0], %1;"
                     :: "l"(src), "r"(49152) : "memory");
    }
    gsync();

    // ======== Phase 2: combine split-K=2 partials (2048 warps) ========
    if (GW < 2048) {
        int row = GW >> 1, half = GW & 1;
        const float4* wr = (const float4*)(comb_W + (size_t)row * H2) + half * 256;
        const float4* c4 = (const float4*)g_cat + half * 256;
        float acc = 0.f;
#pragma unroll
        for (int i = 0; i < 8; i++) {
            int off = lane + 32 * i;
            acc += dot4(wr[off], c4[off]);
        }
        acc = warp_sum(acc);
        if (lane == 0) g_xp[row + half * HID] = acc;
    }
    gsync();

    // ======== Phase 3: x = relu(p0+p1+b) (per-block smem) ; gi = Wih@x ========
    {
        for (int k = t; k < HID; k += NT)
            svec[k] = fmaxf(g_xp[k] + g_xp[k + HID] + comb_b[k], 0.f);
        __syncthreads();
        const float4* x4 = (const float4*)svec;
        for (int r = GW; r < H3; r += NW) {
            const float4* wr = (const float4*)(Wih + (size_t)r * HID);
            float acc = 0.f;
#pragma unroll
            for (int i = 0; i < 8; i++) {
                int off = lane + 32 * i;
                acc += dot4(wr[off], x4[off]);
            }
            acc = warp_sum(acc);
            if (lane == 0) g_gi[r] = acc + bih[r];
        }
    }
    gsync();

    // ======== Phase 4: h_new (redundant) + work-stealing out-proj + online LSE ========
    __syncthreads();   // svec reuse: all phase-3 readers done (gsync above)
    for (int k = t; k < HID; k += NT) {
        float r = 1.f / (1.f + __expf(-(g_gi[k] + g_gh[k])));
        float z = 1.f / (1.f + __expf(-(g_gi[k + HID] + g_gh[k + HID])));
        float n = tanhf(g_gi[k + 2 * HID] + r * g_gh[k + 2 * HID]);
        float hnew = (1.f - z) * n + z * hidden[k];
        svec[k] = hnew;
        if (b == 0) dout[VOCAB + k] = hnew;
    }
    __syncthreads();
    {
        const float4* sv4 = (const float4*)svec;
        float wm = BIG_NEG, ws = 0.f;
        while (true) {
            int g;
            if (lane == 0) g = (int)atomicAdd(&g_work, 1u);
            g = __shfl_sync(0xffffffffu, g, 0);
            if (g >= NGROUPS) break;
            int row0 = g * 8;
            const float4* rp[8];
#pragma unroll
            for (int r = 0; r < 8; r++) {
                int row = row0 + r;
                if (row >= VOCAB) row = VOCAB - 1;
                rp[r] = (const float4*)(out_W + (size_t)row * HID);
            }
            float acc[8];
#pragma unroll
            for (int r = 0; r < 8; r++) acc[r] = 0.f;
#pragma unroll
            for (int i = 0; i < 8; i++) {
                int off = lane + 32 * i;
                float4 v = sv4[off];
#pragma unroll
                for (int r = 0; r < 8; r++) acc[r] += dot4(rp[r][off], v);
            }
#pragma unroll
            for (int r = 0; r < 8; r++) acc[r] = warp_sum(acc[r]);
            if (lane == 0) {
#pragma unroll
                for (int r = 0; r < 8; r++) {
                    int row = row0 + r;
                    if (row < VOCAB) {
                        float l = acc[r] + out_b[row];
                        dout[row] = l;
                        lse_update(wm, ws, l);
                    }
                }
            }
        }
        if (lane == 0) { rm[wid] = wm; rs[wid] = ws; }
    }
    __syncthreads();
    if (t == 0) {
        float m = BIG_NEG, s = 0.f;
#pragma unroll
        for (int i = 0; i < 16; i++) lse_merge(m, s, rm[i], rs[i]);
        g_pm[b] = m;
        g_ps[b] = s;
    }
    gsync();

    // ======== Phase 5: merge partials (redundant) + subtract ========
    {
        float m = BIG_NEG, s = 0.f;
        if (t < GRID) { m = g_pm[t]; s = g_ps[t]; }
        sm[t] = m;
        ss[t] = s;
        __syncthreads();
        for (int o = 128; o; o >>= 1) {
            if (t < o) lse_merge(sm[t], ss[t], sm[t + o], ss[t + o]);
            __syncthreads();
        }
        float lse = sm[0] + __logf(ss[0]);
        for (int i = b * NT + t; i < VOCAB; i += GRID * NT) dout[i] -= lse;
    }
}

// ---------------- launcher ----------------
extern "C" void kernel_launch(void* const* d_in, const int* in_sizes, int n_in,
                              void* d_out, int out_size) {
    const int*   inp    = (const int*)d_in[0];
    const float* hidden = (const float*)d_in[1];
    const float* enc    = (const float*)d_in[2];
    const float* emb    = (const float*)d_in[3];
    const float* attn_W = (const float*)d_in[4];
    const float* attn_b = (const float*)d_in[5];
    const float* comb_W = (const float*)d_in[6];
    const float* comb_b = (const float*)d_in[7];
    const float* Wih    = (const float*)d_in[8];
    const float* Whh    = (const float*)d_in[9];
    const float* bih    = (const float*)d_in[10];
    const float* bhh    = (const float*)d_in[11];
    const float* out_W  = (const float*)d_in[12];
    const float* out_b  = (const float*)d_in[13];
    float* out = (float*)d_out;

    k_fused<<<GRID, NT>>>(inp, hidden, enc, emb, attn_W, attn_b,
                          comb_W, comb_b, Wih, Whh, bih, bhh,
                          out_W, out_b, out);
}